// round 14
// baseline (speedup 1.0000x reference)
#include <cuda_runtime.h>

#define BB 2
#define NN 1024
#define DD 3
#define F1 32
#define F2 64
#define NTH 512
#define NB 256

// Scratch (no allocs allowed). g_h1 feature-major: [batch][feature][point]
__device__ float g_h1[BB*F1*NN];

// ---- packed f32x2 helpers (Blackwell) ----
__device__ __forceinline__ unsigned long long pk2(float lo, float hi) {
    unsigned long long r;
    asm("mov.b64 %0, {%1, %2};" : "=l"(r) : "f"(lo), "f"(hi));
    return r;
}
__device__ __forceinline__ void upk2(unsigned long long v, float& lo, float& hi) {
    asm("mov.b64 {%0, %1}, %2;" : "=f"(lo), "=f"(hi) : "l"(v));
}
__device__ __forceinline__ unsigned long long fma2(unsigned long long a,
                                                   unsigned long long b,
                                                   unsigned long long c) {
    unsigned long long d;
    asm("fma.rn.f32x2 %0, %1, %2, %3;" : "=l"(d) : "l"(a), "l"(b), "l"(c));
    return d;
}

// ---------------------------------------------------------------------------
// Rank-query engine (validated R5/R13): cnt/sum of {c_j > q} via 256-bin
// counting histogram + bucket scan. Ties contribute a + c == 0 -> free.
// ---------------------------------------------------------------------------
struct RankSmem {
    int   cnt[NB];
    int   cur[NB];
    float bsum[NB];
    int   E[NB+1];
    float SS[NB+1];
    float sc[NN];
    float redA[16];
    float redB[16];
};

__device__ void rank_build(RankSmem* S, float c0, float c1,
                           int t, float& mn_out, float& invw_out)
{
    int lane = t & 31, w = t >> 5;

    if (t < NB) { S->cnt[t] = 0; S->bsum[t] = 0.0f; }

    // block min/max of c
    float mnl = fminf(c0, c1), mxl = fmaxf(c0, c1);
#pragma unroll
    for (int o = 16; o > 0; o >>= 1) {
        mnl = fminf(mnl, __shfl_xor_sync(0xffffffffu, mnl, o));
        mxl = fmaxf(mxl, __shfl_xor_sync(0xffffffffu, mxl, o));
    }
    if (lane == 0) { S->redA[w] = mnl; S->redB[w] = mxl; }
    __syncthreads();
    if (t < 16) {
        mnl = S->redA[t]; mxl = S->redB[t];
#pragma unroll
        for (int o = 8; o > 0; o >>= 1) {
            mnl = fminf(mnl, __shfl_xor_sync(0x0000ffffu, mnl, o));
            mxl = fmaxf(mxl, __shfl_xor_sync(0x0000ffffu, mxl, o));
        }
        if (t == 0) { S->redA[0] = mnl; S->redB[0] = (float)NB / fmaxf(mxl - mnl, 1e-30f); }
    }
    __syncthreads();
    float mn = S->redA[0], invw = S->redB[0];
    mn_out = mn; invw_out = invw;

    int b0 = min(max((int)((c0 - mn) * invw), 0), NB-1);
    int b1 = min(max((int)((c1 - mn) * invw), 0), NB-1);
    atomicAdd(&S->cnt[b0], 1);  atomicAdd(&S->bsum[b0], c0);
    atomicAdd(&S->cnt[b1], 1);  atomicAdd(&S->bsum[b1], c1);
    __syncthreads();

    // exclusive scan over NB bins (count + sum), warps 0..7
    int v = 0; float s = 0.0f;
    int vi = 0; float si = 0.0f;
    if (t < NB) {
        v = S->cnt[t]; s = S->bsum[t];
        vi = v; si = s;
#pragma unroll
        for (int o = 1; o < 32; o <<= 1) {
            int   nv = __shfl_up_sync(0xffffffffu, vi, o);
            float ns = __shfl_up_sync(0xffffffffu, si, o);
            if (lane >= o) { vi += nv; si += ns; }
        }
        if (lane == 31) { S->redA[w] = (float)vi; S->redB[w] = si; }
    }
    __syncthreads();
    if (t < 8) {
        float v8 = S->redA[t], s8 = S->redB[t];
        float vv = v8, ss = s8;
#pragma unroll
        for (int o = 1; o < 8; o <<= 1) {
            float nv = __shfl_up_sync(0x000000ffu, vv, o);
            float ns = __shfl_up_sync(0x000000ffu, ss, o);
            if (t >= o) { vv += nv; ss += ns; }
        }
        S->redA[t] = vv - v8;
        S->redB[t] = ss - s8;
    }
    __syncthreads();
    if (t < NB) {
        int   excl  = vi - v + (int)S->redA[w];
        float exclS = si - s + S->redB[w];
        S->E[t] = excl; S->SS[t] = exclS; S->cur[t] = excl;
        if (t == NB-1) { S->E[NB] = excl + v; S->SS[NB] = exclS + s; }
    }
    __syncthreads();

    int p0 = atomicAdd(&S->cur[b0], 1);  S->sc[p0] = c0;
    int p1 = atomicAdd(&S->cur[b1], 1);  S->sc[p1] = c1;
    __syncthreads();
}

__device__ __forceinline__ float rank_query(const RankSmem* S, float a, float cself,
                                            float mn, float invw)
{
    const float scale = 1.0f / (float)(NN - 1);
    float q = -a;
    int qb = min(max((int)((q - mn) * invw), 0), NB-1);
    int beg = S->E[qb], end = S->E[qb+1];
    float cnt = (float)(NN - end);
    float sum = S->SS[NB] - S->SS[qb+1];
    for (int k = beg; k < end; k++) {
        float v = S->sc[k];
        if (v > q) { cnt += 1.0f; sum += v; }
    }
    float self = fmaxf(a + cself, 0.0f);
    return (a * cnt + sum - self) * scale;
}

// ---------------------------------------------------------------------------
// Stage 1: one block per (batch, feature f of 32). Thread t owns points
// (2t, 2t+1). Writes h1 column as coalesced float2. Also zeroes out.
// ---------------------------------------------------------------------------
__global__ __launch_bounds__(NTH) void stage1(
    const float* __restrict__ x,
    const float* __restrict__ W1,
    const float* __restrict__ b1,
    float* __restrict__ out)
{
    __shared__ RankSmem S;

    int t = threadIdx.x;

    // zero output (64 blocks x 512 threads >= 6144 elements)
    int zi = blockIdx.x * NTH + t;
    if (zi < BB*NN*DD) out[zi] = 0.0f;

    int b = blockIdx.x >> 5;
    int f = blockIdx.x & 31;

    float w0 = W1[0*F1+f], w1 = W1[1*F1+f], w2 = W1[2*F1+f];
    float w3 = W1[3*F1+f], w4 = W1[4*F1+f], w5 = W1[5*F1+f];
    float bias = b1[f];
    const float2* xb2 = (const float2*)(x + b*NN*DD);

    // points 2t (even) and 2t+1 (odd): 6 consecutive floats
    float2 v0 = xb2[3*t], v1 = xb2[3*t+1], v2 = xb2[3*t+2];
    float a0 = v0.x*w0 + v0.y*w1 + v1.x*w2 + bias;
    float c0 = v0.x*w3 + v0.y*w4 + v1.x*w5;
    float a1 = v1.y*w0 + v2.x*w1 + v2.y*w2 + bias;
    float c1 = v1.y*w3 + v2.x*w4 + v2.y*w5;

    float mn, invw;
    rank_build(&S, c0, c1, t, mn, invw);

    float2* hout2 = (float2*)(g_h1 + (b*F1 + f)*NN);
    hout2[t] = make_float2(rank_query(&S, a0, c0, mn, invw),
                           rank_query(&S, a1, c1, mn, invw));
}

// ---------------------------------------------------------------------------
// Stage 2 (fused with block-3 closed form): one block per (batch, f2 of 64).
// Thread t owns points (2t, 2t+1): float2 h1 loads + packed f32x2 FMA.
//   out[i,d] += h2[i]*(Wt[f2,d] - Wb[f2,d]*inv) + Hsum*Wb[f2,d]*inv + b3[d]/F2
// ---------------------------------------------------------------------------
__global__ __launch_bounds__(NTH) void stage2_fused(
    const float* __restrict__ W2,
    const float* __restrict__ b2,
    const float* __restrict__ W3,
    const float* __restrict__ b3,
    float* __restrict__ out)
{
    __shared__ RankSmem S;
    __shared__ unsigned long long wt2[F1], wb2[F1];   // packed {w,w}

    int t = threadIdx.x;
    int b = blockIdx.x >> 6;
    int f2 = blockIdx.x & 63;

    if (t < F1) {
        float w_top = W2[t*F2 + f2];
        float w_bot = W2[(F1 + t)*F2 + f2];
        wt2[t] = pk2(w_top, w_top);
        wb2[t] = pk2(w_bot, w_bot);
    }
    float bias = b2[f2];
    __syncthreads();

    // projection: packed over point pair (2t, 2t+1)
    const float2* h1b2 = (const float2*)(g_h1 + b*F1*NN);
    unsigned long long aP = pk2(bias, bias);
    unsigned long long cP = pk2(0.0f, 0.0f);
#pragma unroll
    for (int f = 0; f < F1; f++) {
        float2 hv = __ldg(&h1b2[f*(NN/2) + t]);    // cross-kernel data: safe
        unsigned long long hP = pk2(hv.x, hv.y);
        aP = fma2(hP, wt2[f], aP);
        cP = fma2(hP, wb2[f], cP);
    }
    float a0, a1, c0, c1;
    upk2(aP, a0, a1);
    upk2(cP, c0, c1);

    float mn, invw;
    rank_build(&S, c0, c1, t, mn, invw);

    float h0 = rank_query(&S, a0, c0, mn, invw);
    float h1 = rank_query(&S, a1, c1, mn, invw);

    // block-reduce Hsum = sum_i h2[i]
    float hloc = h0 + h1;
    __syncthreads();
    int lane = t & 31, w = t >> 5;
#pragma unroll
    for (int o = 16; o > 0; o >>= 1)
        hloc += __shfl_xor_sync(0xffffffffu, hloc, o);
    if (lane == 0) S.redA[w] = hloc;
    __syncthreads();
    if (t < 16) {
        float v = S.redA[t];
#pragma unroll
        for (int o = 8; o > 0; o >>= 1)
            v += __shfl_xor_sync(0x0000ffffu, v, o);
        if (t == 0) S.redA[0] = v;
    }
    __syncthreads();
    float Hsum = S.redA[0];

    // direct output commit (F2=64 blocks contribute per output point)
    const float inv = 1.0f / (float)(NN - 1);
    float coef[DD], addc[DD];
#pragma unroll
    for (int d = 0; d < DD; d++) {
        float wtd = W3[f2*DD + d];
        float wbd = W3[(F2 + f2)*DD + d];
        coef[d] = wtd - wbd*inv;
        addc[d] = Hsum*wbd*inv + b3[d]*(1.0f/(float)F2);
    }
    float* o0 = out + ((size_t)b*NN + 2*t)*DD;     // 6 consecutive floats
#pragma unroll
    for (int d = 0; d < DD; d++) {
        atomicAdd(o0 + d,      h0*coef[d] + addc[d]);
        atomicAdd(o0 + DD + d, h1*coef[d] + addc[d]);
    }
}

// ---------------------------------------------------------------------------
extern "C" void kernel_launch(void* const* d_in, const int* in_sizes, int n_in,
                              void* d_out, int out_size)
{
    const float* x  = (const float*)d_in[0];   // (2, 3072)
    const float* W1 = (const float*)d_in[1];   // (6, 32)
    const float* b1 = (const float*)d_in[2];   // (32,)
    const float* W2 = (const float*)d_in[3];   // (64, 64)
    const float* b2 = (const float*)d_in[4];   // (64,)
    const float* W3 = (const float*)d_in[5];   // (128, 3)
    const float* b3 = (const float*)d_in[6];   // (3,)
    float* out = (float*)d_out;

    stage1<<<BB*F1, NTH>>>(x, W1, b1, out);              // 64 blocks
    stage2_fused<<<BB*F2, NTH>>>(W2, b2, W3, b3, out);   // 128 blocks
}